// round 2
// baseline (speedup 1.0000x reference)
#include <cuda_runtime.h>
#include <math.h>

#define BB 16
#define TT 500
#define CC 2048
#define SN 64
#define SD 512

// Scratch (no cudaMalloc allowed): exp(den_logA) and per-batch log-likelihoods.
__device__ __align__(16) float g_Pden[SD * SD];
__device__ float g_llh[2 * BB];   // [0..15] den, [16..31] num

__global__ void prep_expA_kernel(const float* __restrict__ logA) {
    int i = blockIdx.x * blockDim.x + threadIdx.x;
    g_Pden[i] = __expf(logA[i]);
}

__device__ __forceinline__ float warp_max(float v) {
#pragma unroll
    for (int o = 16; o > 0; o >>= 1) v = fmaxf(v, __shfl_xor_sync(0xffffffffu, v, o));
    return v;
}
__device__ __forceinline__ float warp_sum(float v) {
#pragma unroll
    for (int o = 16; o > 0; o >>= 1) v += __shfl_xor_sync(0xffffffffu, v, o);
    return v;
}

__device__ __forceinline__ float clip30(float v) {
    return fminf(fmaxf(v, -30.f), 30.f);
}

// ---------------------------------------------------------------------------
// Denominator: shared FSM, S=512. One CTA (512 threads) per batch.
// alpha recursion in linear space with per-step max normalization:
//   u[s] = exp(alpha[s] - m);  v[j] = sum_s u[s] * P[s,j];
//   alpha'[j] = m + log(v[j]) + em_t[j]
// ---------------------------------------------------------------------------
__device__ void den_path(int b, const float* __restrict__ x,
                         const int* __restrict__ seqlens,
                         const float* __restrict__ ls,
                         const float* __restrict__ lf,
                         const int* __restrict__ ids_g) {
    __shared__ __align__(16) float u_sh[SD];
    __shared__ float alpha_sh[SD];
    __shared__ float em_sh[2][SD];
    __shared__ __align__(16) float red[4][SD];
    __shared__ float warp_red[16];
    __shared__ float m_sh;

    const int tid = threadIdx.x;
    const int lane = tid & 31, wid = tid >> 5;
    const int g = tid >> 7;              // row class 0..3
    const int c4 = (tid & 127) << 2;     // output column base (4 cols/thread)
    const int myid = ids_g[tid];
    const int L = seqlens[b];
    const float* xb = x + (size_t)b * TT * CC;

    // t = 0
    alpha_sh[tid] = ls[tid] + clip30(xb[myid]);
    float emn = (L > 1) ? xb[CC + myid] : 0.f;   // prefetch em(t=1)
    __syncthreads();

    for (int t = 1; t < L; ++t) {
        em_sh[t & 1][tid] = clip30(emn);
        float emn2 = (t + 1 < L) ? xb[(size_t)(t + 1) * CC + myid] : 0.f;

        // global max over alpha
        float a = alpha_sh[tid];
        float wm = warp_max(a);
        if (lane == 0) warp_red[wid] = wm;
        __syncthreads();
        if (tid < 32) {
            float v = (tid < 16) ? warp_red[tid] : -1e30f;
            v = warp_max(v);
            if (tid == 0) m_sh = v;
        }
        __syncthreads();
        float m = m_sh;
        u_sh[tid] = __expf(a - m);
        emn = emn2;
        __syncthreads();

        // matvec: v[c4..c4+3] partial over rows s ≡ g (mod 4)
        float acc0 = 0.f, acc1 = 0.f, acc2 = 0.f, acc3 = 0.f;
#pragma unroll 8
        for (int s = g; s < SD; s += 4) {
            float us = u_sh[s];
            float4 p = *(const float4*)&g_Pden[s * SD + c4];
            acc0 = fmaf(us, p.x, acc0);
            acc1 = fmaf(us, p.y, acc1);
            acc2 = fmaf(us, p.z, acc2);
            acc3 = fmaf(us, p.w, acc3);
        }
        *(float4*)&red[g][c4] = make_float4(acc0, acc1, acc2, acc3);
        __syncthreads();
        if (g == 0) {
#pragma unroll
            for (int k = 0; k < 4; ++k) {
                int col = c4 + k;
                float v = red[0][col] + red[1][col] + red[2][col] + red[3][col];
                alpha_sh[col] = m + __logf(v) + em_sh[t & 1][col];
            }
        }
        __syncthreads();
    }

    // llh = logsumexp(alpha + log_final)
    float a = alpha_sh[tid] + lf[tid];
    float wm = warp_max(a);
    if (lane == 0) warp_red[wid] = wm;
    __syncthreads();
    if (tid < 32) {
        float v = (tid < 16) ? warp_red[tid] : -1e30f;
        v = warp_max(v);
        if (tid == 0) m_sh = v;
    }
    __syncthreads();
    float m = m_sh;
    float e = __expf(a - m);
    float ws = warp_sum(e);
    __syncthreads();  // all reads of warp_red done before reuse
    if (lane == 0) warp_red[wid] = ws;
    __syncthreads();
    if (tid == 0) {
        float s = 0.f;
        for (int i = 0; i < 16; ++i) s += warp_red[i];
        g_llh[b] = m + __logf(s);
    }
}

// ---------------------------------------------------------------------------
// Numerator: per-batch FSM, S=64. One CTA (512 threads) per batch.
// P (64x64, 16KB) held in shared memory.
// ---------------------------------------------------------------------------
__device__ void num_path(int b, const float* __restrict__ x,
                         const int* __restrict__ seqlens,
                         const float* __restrict__ logA,
                         const float* __restrict__ ls,
                         const float* __restrict__ lf,
                         const int* __restrict__ ids_g) {
    __shared__ __align__(16) float Pn[SN * SN];
    __shared__ __align__(16) float u_n[SN];
    __shared__ float alpha_n[SN];
    __shared__ float em_n[2][SN];
    __shared__ __align__(16) float redn[32][SN];
    __shared__ float wred[2];

    const int tid = threadIdx.x;
    const int lane = tid & 31;
    const int g = tid >> 4;              // row class 0..31
    const int c4 = (tid & 15) << 2;      // column base
    const int L = seqlens[b];
    const float* xb = x + (size_t)b * TT * CC;

    for (int i = tid; i < SN * SN; i += 512)
        Pn[i] = __expf(logA[(size_t)b * SN * SN + i]);

    int myid = 0;
    float emn = 0.f;
    if (tid < SN) {
        myid = ids_g[b * SN + tid];
        alpha_n[tid] = ls[b * SN + tid] + clip30(xb[myid]);
        emn = (L > 1) ? xb[CC + myid] : 0.f;
    }
    __syncthreads();

    for (int t = 1; t < L; ++t) {
        if (tid < SN) em_n[t & 1][tid] = clip30(emn);
        float emn2 = (tid < SN && t + 1 < L) ? xb[(size_t)(t + 1) * CC + myid] : 0.f;

        float a = (tid < SN) ? alpha_n[tid] : -1e30f;
        if (tid < 64) {
            float wm = warp_max(a);
            if (lane == 0) wred[tid >> 5] = wm;
        }
        __syncthreads();
        float m = fmaxf(wred[0], wred[1]);
        if (tid < SN) u_n[tid] = __expf(a - m);
        emn = emn2;
        __syncthreads();

        float acc0 = 0.f, acc1 = 0.f, acc2 = 0.f, acc3 = 0.f;
#pragma unroll
        for (int s = g; s < SN; s += 32) {
            float us = u_n[s];
            float4 p = *(const float4*)&Pn[s * SN + c4];
            acc0 = fmaf(us, p.x, acc0);
            acc1 = fmaf(us, p.y, acc1);
            acc2 = fmaf(us, p.z, acc2);
            acc3 = fmaf(us, p.w, acc3);
        }
        *(float4*)&redn[g][c4] = make_float4(acc0, acc1, acc2, acc3);
        __syncthreads();
        if (tid < SN) {
            float v = 0.f;
#pragma unroll
            for (int k = 0; k < 32; ++k) v += redn[k][tid];
            alpha_n[tid] = m + __logf(v) + em_n[t & 1][tid];
        }
        __syncthreads();
    }

    // llh = logsumexp(alpha + log_final)
    float a = (tid < SN) ? alpha_n[tid] + lf[b * SN + tid] : -1e30f;
    if (tid < 64) {
        float wm = warp_max(a);
        if (lane == 0) wred[tid >> 5] = wm;
    }
    __syncthreads();
    float m = fmaxf(wred[0], wred[1]);
    float e = (tid < SN) ? __expf(a - m) : 0.f;
    __syncthreads();  // all reads of wred done before reuse
    if (tid < 64) {
        float ws = warp_sum(e);
        if (lane == 0) wred[tid >> 5] = ws;
    }
    __syncthreads();
    if (tid == 0) g_llh[BB + b] = m + __logf(wred[0] + wred[1]);
}

__global__ void __launch_bounds__(512) fsm_kernel(
    const float* __restrict__ x, const int* __restrict__ seqlens,
    const float* __restrict__ num_logA, const float* __restrict__ num_ls,
    const float* __restrict__ num_lf, const int* __restrict__ num_ids,
    const float* __restrict__ den_ls, const float* __restrict__ den_lf,
    const int* __restrict__ den_ids) {
    int bx = blockIdx.x;
    if (bx < BB)
        den_path(bx, x, seqlens, den_ls, den_lf, den_ids);
    else
        num_path(bx - BB, x, seqlens, num_logA, num_ls, num_lf, num_ids);
}

__global__ void finalize_kernel(float* __restrict__ out) {
    float sden = 0.f, snum = 0.f;
    for (int i = 0; i < BB; ++i) {
        sden += g_llh[i];
        snum += g_llh[BB + i];
    }
    out[0] = -(snum - sden);
}

extern "C" void kernel_launch(void* const* d_in, const int* in_sizes, int n_in,
                              void* d_out, int out_size) {
    const float* x        = (const float*)d_in[0];
    const int*   seqlens  = (const int*)d_in[1];
    const float* num_logA = (const float*)d_in[2];
    const float* num_ls   = (const float*)d_in[3];
    const float* num_lf   = (const float*)d_in[4];
    const int*   num_ids  = (const int*)d_in[5];
    const float* den_logA = (const float*)d_in[6];
    const float* den_ls   = (const float*)d_in[7];
    const float* den_lf   = (const float*)d_in[8];
    const int*   den_ids  = (const int*)d_in[9];

    prep_expA_kernel<<<SD, SD>>>(den_logA);
    fsm_kernel<<<2 * BB, 512>>>(x, seqlens, num_logA, num_ls, num_lf, num_ids,
                                den_ls, den_lf, den_ids);
    finalize_kernel<<<1, 1>>>((float*)d_out);
}

// round 4
// speedup vs baseline: 11.0610x; 11.0610x over previous
#include <cuda_runtime.h>
#include <cstdint>
#include <math.h>

#define BB 16
#define TT 500
#define CC 2048
#define SN 64
#define SD 512
#define CLU 8          // CTAs per den cluster
#define COLS_PER_CTA (SD / CLU)   // 64

__device__ float g_llh[2 * BB];   // [0..15] den, [16..31] num

__device__ __forceinline__ float warp_max(float v) {
#pragma unroll
    for (int o = 16; o > 0; o >>= 1) v = fmaxf(v, __shfl_xor_sync(0xffffffffu, v, o));
    return v;
}
__device__ __forceinline__ float warp_sum(float v) {
#pragma unroll
    for (int o = 16; o > 0; o >>= 1) v += __shfl_xor_sync(0xffffffffu, v, o);
    return v;
}
__device__ __forceinline__ float clip30(float v) {
    return fminf(fmaxf(v, -30.f), 30.f);
}

__device__ __forceinline__ uint32_t smem_u32(const void* p) {
    uint32_t a;
    asm("{ .reg .u64 t; cvta.to.shared.u64 t, %1; cvt.u32.u64 %0, t; }" : "=r"(a) : "l"(p));
    return a;
}
__device__ __forceinline__ void st_cluster_f32(uint32_t local_addr, int rank, float v) {
    uint32_t rem;
    asm volatile("mapa.shared::cluster.u32 %0, %1, %2;" : "=r"(rem) : "r"(local_addr), "r"(rank));
    asm volatile("st.shared::cluster.f32 [%0], %1;" :: "r"(rem), "f"(v) : "memory");
}
__device__ __forceinline__ void cluster_sync_() {
    asm volatile("barrier.cluster.arrive.aligned;" ::: "memory");
    asm volatile("barrier.cluster.wait.aligned;" ::: "memory");
}
__device__ __forceinline__ uint32_t ctarank_() {
    uint32_t r;
    asm("mov.u32 %0, %%cluster_ctarank;" : "=r"(r));
    return r;
}

// ---------------------------------------------------------------------------
// Denominator: one 8-CTA cluster per batch. Each CTA owns 64 output columns;
// its 512x64 slice of P = exp(den_logA) lives in registers (64/thread).
// Per step: u = exp(alpha - max); v = u @ P_slice; alpha' = m + log(v) + em;
// new alphas broadcast to all peers via DSMEM; one cluster.sync per step.
// ---------------------------------------------------------------------------
__global__ void __launch_bounds__(512, 1) __cluster_dims__(CLU, 1, 1)
den_kernel(const float* __restrict__ x, const int* __restrict__ seqlens,
           const float* __restrict__ logA, const float* __restrict__ ls,
           const float* __restrict__ lf, const int* __restrict__ ids_g) {
    __shared__ __align__(16) float alpha_buf[2][SD];
    __shared__ __align__(16) float u_sh[SD];
    __shared__ float red_sh[CLU * COLS_PER_CTA];   // [rg][col]
    __shared__ float warp_red[16];
    __shared__ float m_sh;

    const int tid  = threadIdx.x;
    const int lane = tid & 31, wid = tid >> 5;
    const int c    = tid & 63;        // local column
    const int rg   = tid >> 6;        // row group 0..7 (64 rows each)
    const int r    = (int)ctarank_();
    const int b    = blockIdx.x / CLU;
    const int j    = r * COLS_PER_CTA + c;   // global output column
    const int L    = seqlens[b];
    const float* xb = x + (size_t)b * TT * CC;

    // P slice in registers: preg[k] = exp(logA[rg*64+k][j])
    float preg[64];
#pragma unroll
    for (int k = 0; k < 64; ++k)
        preg[k] = __expf(logA[(size_t)(rg * 64 + k) * SD + j]);

    // t = 0 init (threads 0..63 own this CTA's 64 columns)
    int myid = 0;
    float emn = 0.f;
    const int jcol = r * COLS_PER_CTA + tid;   // valid when tid < 64
    if (tid < 64) {
        myid = ids_g[jcol];
        float a0 = ls[jcol] + clip30(xb[myid]);
#pragma unroll
        for (int pr = 0; pr < CLU; ++pr)
            st_cluster_f32(smem_u32(&alpha_buf[0][jcol]), pr, a0);
        emn = (L > 1) ? xb[CC + myid] : 0.f;
    }
    cluster_sync_();

    int p = 0;
    for (int t = 1; t < L; ++t) {
        // global max over alpha (replicated in every CTA)
        float a = alpha_buf[p][tid];
        float wm = warp_max(a);
        if (lane == 0) warp_red[wid] = wm;
        __syncthreads();
        if (tid < 32) {
            float v = (tid < 16) ? warp_red[tid] : -1e30f;
            v = warp_max(v);
            if (tid == 0) m_sh = v;
        }
        __syncthreads();
        const float m = m_sh;
        u_sh[tid] = __expf(a - m);

        float em_t = clip30(emn);
        if (tid < 64) emn = (t + 1 < L) ? xb[(size_t)(t + 1) * CC + myid] : 0.f;
        __syncthreads();

        // matvec partial: acc = sum_k u[rg*64+k] * P[rg*64+k][j]
        float acc = 0.f;
        const float4* u4 = (const float4*)&u_sh[rg * 64];
#pragma unroll
        for (int k4 = 0; k4 < 16; ++k4) {
            float4 u = u4[k4];
            acc = fmaf(u.x, preg[4 * k4 + 0], acc);
            acc = fmaf(u.y, preg[4 * k4 + 1], acc);
            acc = fmaf(u.z, preg[4 * k4 + 2], acc);
            acc = fmaf(u.w, preg[4 * k4 + 3], acc);
        }
        red_sh[rg * COLS_PER_CTA + c] = acc;
        __syncthreads();

        if (tid < 64) {
            float v = 0.f;
#pragma unroll
            for (int g2 = 0; g2 < CLU; ++g2) v += red_sh[g2 * COLS_PER_CTA + tid];
            float an = m + __logf(v) + em_t;
#pragma unroll
            for (int pr = 0; pr < CLU; ++pr)
                st_cluster_f32(smem_u32(&alpha_buf[1 - p][jcol]), pr, an);
        }
        cluster_sync_();
        p ^= 1;
    }

    // llh = logsumexp(alpha + log_final); rank 0 computes (has full alpha)
    if (r == 0) {
        float a = alpha_buf[p][tid] + lf[tid];
        float wm = warp_max(a);
        if (lane == 0) warp_red[wid] = wm;
        __syncthreads();
        if (tid < 32) {
            float v = (tid < 16) ? warp_red[tid] : -1e30f;
            v = warp_max(v);
            if (tid == 0) m_sh = v;
        }
        __syncthreads();
        float m = m_sh;
        float e = __expf(a - m);
        float ws = warp_sum(e);
        __syncthreads();
        if (lane == 0) warp_red[wid] = ws;
        __syncthreads();
        if (tid == 0) {
            float s = 0.f;
            for (int i = 0; i < 16; ++i) s += warp_red[i];
            g_llh[b] = m + __logf(s);
        }
    }
    cluster_sync_();   // no CTA exits while peers may still receive its DSMEM traffic
}

// ---------------------------------------------------------------------------
// Numerator: per-batch FSM, S=64. One CTA (512 threads) per batch.
// ---------------------------------------------------------------------------
__global__ void __launch_bounds__(512) num_kernel(
    const float* __restrict__ x, const int* __restrict__ seqlens,
    const float* __restrict__ logA, const float* __restrict__ ls,
    const float* __restrict__ lf, const int* __restrict__ ids_g) {
    __shared__ __align__(16) float Pn[SN * SN];
    __shared__ __align__(16) float u_n[SN];
    __shared__ float alpha_n[SN];
    __shared__ float em_n[2][SN];
    __shared__ __align__(16) float redn[32][SN];
    __shared__ float wred[2];

    const int b = blockIdx.x;
    const int tid = threadIdx.x;
    const int lane = tid & 31;
    const int g = tid >> 4;              // row class 0..31
    const int c4 = (tid & 15) << 2;      // column base
    const int L = seqlens[b];
    const float* xb = x + (size_t)b * TT * CC;

    for (int i = tid; i < SN * SN; i += 512)
        Pn[i] = __expf(logA[(size_t)b * SN * SN + i]);

    int myid = 0;
    float emn = 0.f;
    if (tid < SN) {
        myid = ids_g[b * SN + tid];
        alpha_n[tid] = ls[b * SN + tid] + clip30(xb[myid]);
        emn = (L > 1) ? xb[CC + myid] : 0.f;
    }
    __syncthreads();

    for (int t = 1; t < L; ++t) {
        if (tid < SN) em_n[t & 1][tid] = clip30(emn);
        float emn2 = (tid < SN && t + 1 < L) ? xb[(size_t)(t + 1) * CC + myid] : 0.f;

        float a = (tid < SN) ? alpha_n[tid] : -1e30f;
        if (tid < 64) {
            float wm = warp_max(a);
            if (lane == 0) wred[tid >> 5] = wm;
        }
        __syncthreads();
        float m = fmaxf(wred[0], wred[1]);
        if (tid < SN) u_n[tid] = __expf(a - m);
        emn = emn2;
        __syncthreads();

        float acc0 = 0.f, acc1 = 0.f, acc2 = 0.f, acc3 = 0.f;
#pragma unroll
        for (int s = g; s < SN; s += 32) {
            float us = u_n[s];
            float4 p = *(const float4*)&Pn[s * SN + c4];
            acc0 = fmaf(us, p.x, acc0);
            acc1 = fmaf(us, p.y, acc1);
            acc2 = fmaf(us, p.z, acc2);
            acc3 = fmaf(us, p.w, acc3);
        }
        *(float4*)&redn[g][c4] = make_float4(acc0, acc1, acc2, acc3);
        __syncthreads();
        if (tid < SN) {
            float v = 0.f;
#pragma unroll
            for (int k = 0; k < 32; ++k) v += redn[k][tid];
            alpha_n[tid] = m + __logf(v) + em_n[t & 1][tid];
        }
        __syncthreads();
    }

    float a = (tid < SN) ? alpha_n[tid] + lf[b * SN + tid] : -1e30f;
    if (tid < 64) {
        float wm = warp_max(a);
        if (lane == 0) wred[tid >> 5] = wm;
    }
    __syncthreads();
    float m = fmaxf(wred[0], wred[1]);
    float e = (tid < SN) ? __expf(a - m) : 0.f;
    __syncthreads();
    if (tid < 64) {
        float ws = warp_sum(e);
        if (lane == 0) wred[tid >> 5] = ws;
    }
    __syncthreads();
    if (tid == 0) g_llh[BB + b] = m + __logf(wred[0] + wred[1]);
}

__global__ void finalize_kernel(float* __restrict__ out) {
    float sden = 0.f, snum = 0.f;
    for (int i = 0; i < BB; ++i) {
        sden += g_llh[i];
        snum += g_llh[BB + i];
    }
    out[0] = -(snum - sden);
}

extern "C" void kernel_launch(void* const* d_in, const int* in_sizes, int n_in,
                              void* d_out, int out_size) {
    const float* x        = (const float*)d_in[0];
    const int*   seqlens  = (const int*)d_in[1];
    const float* num_logA = (const float*)d_in[2];
    const float* num_ls   = (const float*)d_in[3];
    const float* num_lf   = (const float*)d_in[4];
    const int*   num_ids  = (const int*)d_in[5];
    const float* den_logA = (const float*)d_in[6];
    const float* den_ls   = (const float*)d_in[7];
    const float* den_lf   = (const float*)d_in[8];
    const int*   den_ids  = (const int*)d_in[9];

    num_kernel<<<BB, 512>>>(x, seqlens, num_logA, num_ls, num_lf, num_ids);
    den_kernel<<<BB * CLU, 512>>>(x, seqlens, den_logA, den_ls, den_lf, den_ids);
    finalize_kernel<<<1, 1>>>((float*)d_out);
}

// round 5
// speedup vs baseline: 16.0496x; 1.4510x over previous
#include <cuda_runtime.h>
#include <cstdint>
#include <math.h>

#define BB 16
#define TT 500
#define CC 2048
#define SN 64
#define SD 512
#define CLU 8                      // CTAs per den cluster
#define CPC (SD / CLU)             // 64 columns per den CTA

typedef unsigned long long ull;

__device__ float g_llh[2 * BB];    // [0..15] den, [16..31] num

__device__ __forceinline__ float warp_max(float v) {
#pragma unroll
    for (int o = 16; o > 0; o >>= 1) v = fmaxf(v, __shfl_xor_sync(0xffffffffu, v, o));
    return v;
}
__device__ __forceinline__ float warp_sum(float v) {
#pragma unroll
    for (int o = 16; o > 0; o >>= 1) v += __shfl_xor_sync(0xffffffffu, v, o);
    return v;
}
__device__ __forceinline__ float clip30(float v) {
    return fminf(fmaxf(v, -30.f), 30.f);
}
__device__ __forceinline__ uint32_t smem_u32(const void* p) {
    uint32_t a;
    asm("{ .reg .u64 t; cvta.to.shared.u64 t, %1; cvt.u32.u64 %0, t; }" : "=r"(a) : "l"(p));
    return a;
}
__device__ __forceinline__ void st_cluster_f32(uint32_t local_addr, int rank, float v) {
    uint32_t rem;
    asm volatile("mapa.shared::cluster.u32 %0, %1, %2;" : "=r"(rem) : "r"(local_addr), "r"(rank));
    asm volatile("st.shared::cluster.f32 [%0], %1;" :: "r"(rem), "f"(v) : "memory");
}
__device__ __forceinline__ void cluster_sync_() {
    asm volatile("barrier.cluster.arrive.aligned;" ::: "memory");
    asm volatile("barrier.cluster.wait.aligned;" ::: "memory");
}
__device__ __forceinline__ uint32_t ctarank_() {
    uint32_t r;
    asm("mov.u32 %0, %%cluster_ctarank;" : "=r"(r));
    return r;
}
// packed dual-fp32 fma: d = a * b + d (lanewise on the two 32-bit halves)
__device__ __forceinline__ void fma2(ull& d, ull a, ull b) {
    asm("fma.rn.f32x2 %0, %1, %2, %0;" : "+l"(d) : "l"(a), "l"(b));
}

// ---------------------------------------------------------------------------
// Denominator: one 8-CTA cluster per batch. Each CTA owns 64 output columns;
// its 512x64 slice of P = exp(den_logA) lives in registers as 32 packed f32x2
// (2 columns x 32 rows per thread; 16 row-groups x 32 col-pairs = 512 threads).
// Per step: m = max of 16 broadcast warp-maxima; u = exp(alpha-m) stored as
// packed {u,u}; matvec with fma.rn.f32x2; finalize cols + broadcast alphas and
// warp maxima to all 8 peers via DSMEM; one cluster.sync per step.
// ---------------------------------------------------------------------------
__device__ void den_path(const float* __restrict__ x, const int* __restrict__ seqlens,
                         const float* __restrict__ logA, const float* __restrict__ ls,
                         const float* __restrict__ lf, const int* __restrict__ ids_g) {
    __shared__ __align__(16) float alpha_buf[2][SD];
    __shared__ __align__(16) ull u2_sh[SD];          // packed {u,u}
    __shared__ __align__(16) ull red2[16 * 32];      // [rg][cp] -> cols {2cp,2cp+1}
    __shared__ float m_arr[2][16];                   // 8 CTAs x 2 producer warps
    __shared__ float warp_red[16];
    __shared__ float m_sh;

    const int tid  = threadIdx.x;
    const int lane = tid & 31, wid = tid >> 5;
    const int rg   = tid >> 5;          // row group 0..15 (32 rows each)
    const int cp   = tid & 31;          // column pair 0..31
    const int r    = (int)ctarank_();
    const int b    = blockIdx.x / CLU;
    const int j0   = r * CPC + 2 * cp;  // first of this thread's 2 global cols
    const int L    = seqlens[b];
    const float* xb = x + (size_t)b * TT * CC;

    // P slice in registers, packed per column pair
    ull pr[32];
#pragma unroll
    for (int k = 0; k < 32; ++k) {
        float2 p2;
        p2.x = __expf(logA[(size_t)(rg * 32 + k) * SD + j0]);
        p2.y = __expf(logA[(size_t)(rg * 32 + k) * SD + j0 + 1]);
        pr[k] = *(ull*)&p2;
    }

    // t = 0 init (threads 0..63 own this CTA's 64 columns)
    int myid = 0;
    float emn = 0.f;
    const int jcol = r * CPC + tid;     // valid when tid < 64
    if (tid < 64) {
        myid = ids_g[jcol];
        float a0 = ls[jcol] + clip30(xb[myid]);
#pragma unroll
        for (int q = 0; q < CLU; ++q)
            st_cluster_f32(smem_u32(&alpha_buf[0][jcol]), q, a0);
        float wm = warp_max(a0);
        if (lane == 0) {
#pragma unroll
            for (int q = 0; q < CLU; ++q)
                st_cluster_f32(smem_u32(&m_arr[0][r * 2 + wid]), q, wm);
        }
        emn = (L > 1) ? xb[CC + myid] : 0.f;
    }
    cluster_sync_();

    int p = 0;
    for (int t = 1; t < L; ++t) {
        // combine 16 broadcast warp maxima (warp 0 only)
        if (tid < 32) {
            float v = (lane < 16) ? m_arr[p][lane] : -1e30f;
            v = warp_max(v);
            if (lane == 0) m_sh = v;
        }
        __syncthreads();
        const float m = m_sh;
        float a = alpha_buf[p][tid];
        float e = __expf(a - m);
        float2 ee = make_float2(e, e);
        u2_sh[tid] = *(ull*)&ee;
        float em_t = clip30(emn);
        if (tid < 64) emn = (t + 1 < L) ? xb[(size_t)(t + 1) * CC + myid] : 0.f;
        __syncthreads();

        // matvec partial over 32 rows, 2 columns (packed)
        ull acc = 0ull;
        const ulonglong2* uu = (const ulonglong2*)&u2_sh[rg * 32];
#pragma unroll
        for (int k2 = 0; k2 < 16; ++k2) {
            ulonglong2 u = uu[k2];
            fma2(acc, u.x, pr[2 * k2]);
            fma2(acc, u.y, pr[2 * k2 + 1]);
        }
        red2[rg * 32 + cp] = acc;
        __syncthreads();

        if (tid < 64) {
            const float* rf = (const float*)red2;   // col index = tid at offset g*64+tid
            float v = 0.f;
#pragma unroll
            for (int g2 = 0; g2 < 16; ++g2) v += rf[g2 * 64 + tid];
            float an = m + __logf(v) + em_t;
#pragma unroll
            for (int q = 0; q < CLU; ++q)
                st_cluster_f32(smem_u32(&alpha_buf[1 - p][jcol]), q, an);
            float wm = warp_max(an);
            if (lane == 0) {
#pragma unroll
                for (int q = 0; q < CLU; ++q)
                    st_cluster_f32(smem_u32(&m_arr[1 - p][r * 2 + wid]), q, wm);
            }
        }
        cluster_sync_();
        p ^= 1;
    }

    // llh = logsumexp(alpha + log_final); rank 0 computes (has full alpha)
    if (r == 0) {
        float a = alpha_buf[p][tid] + lf[tid];
        float wm = warp_max(a);
        if (lane == 0) warp_red[wid] = wm;
        __syncthreads();
        if (tid < 32) {
            float v = (tid < 16) ? warp_red[tid] : -1e30f;
            v = warp_max(v);
            if (tid == 0) m_sh = v;
        }
        __syncthreads();
        float m = m_sh;
        float e = __expf(a - m);
        float ws = warp_sum(e);
        __syncthreads();
        if (lane == 0) warp_red[wid] = ws;
        __syncthreads();
        if (tid == 0) {
            float s = 0.f;
            for (int i = 0; i < 16; ++i) s += warp_red[i];
            g_llh[b] = m + __logf(s);
        }
    }
    cluster_sync_();   // no CTA exits while peers may still receive its DSMEM traffic
}

// ---------------------------------------------------------------------------
// Numerator: per-batch FSM, S=64. One CTA (512 threads) per batch.
// Runs on its own SMs in parallel with den (fused grid) -> fully hidden.
// ---------------------------------------------------------------------------
__device__ void num_path(int b, const float* __restrict__ x,
                         const int* __restrict__ seqlens,
                         const float* __restrict__ logA,
                         const float* __restrict__ ls,
                         const float* __restrict__ lf,
                         const int* __restrict__ ids_g) {
    __shared__ __align__(16) float Pn[SN * SN];
    __shared__ __align__(16) float u_n[SN];
    __shared__ float alpha_n[SN];
    __shared__ float em_n[2][SN];
    __shared__ __align__(16) float redn[32][SN];
    __shared__ float wred[2];

    const int tid = threadIdx.x;
    const int lane = tid & 31;
    const int g = tid >> 4;              // row class 0..31
    const int c4 = (tid & 15) << 2;      // column base
    const int L = seqlens[b];
    const float* xb = x + (size_t)b * TT * CC;

    for (int i = tid; i < SN * SN; i += 512)
        Pn[i] = __expf(logA[(size_t)b * SN * SN + i]);

    int myid = 0;
    float emn = 0.f;
    if (tid < SN) {
        myid = ids_g[b * SN + tid];
        alpha_n[tid] = ls[b * SN + tid] + clip30(xb[myid]);
        emn = (L > 1) ? xb[CC + myid] : 0.f;
    }
    __syncthreads();

    for (int t = 1; t < L; ++t) {
        if (tid < SN) em_n[t & 1][tid] = clip30(emn);
        float emn2 = (tid < SN && t + 1 < L) ? xb[(size_t)(t + 1) * CC + myid] : 0.f;

        float a = (tid < SN) ? alpha_n[tid] : -1e30f;
        if (tid < 64) {
            float wm = warp_max(a);
            if (lane == 0) wred[tid >> 5] = wm;
        }
        __syncthreads();
        float m = fmaxf(wred[0], wred[1]);
        if (tid < SN) u_n[tid] = __expf(a - m);
        emn = emn2;
        __syncthreads();

        float acc0 = 0.f, acc1 = 0.f, acc2 = 0.f, acc3 = 0.f;
#pragma unroll
        for (int s = g; s < SN; s += 32) {
            float us = u_n[s];
            float4 pv = *(const float4*)&Pn[s * SN + c4];
            acc0 = fmaf(us, pv.x, acc0);
            acc1 = fmaf(us, pv.y, acc1);
            acc2 = fmaf(us, pv.z, acc2);
            acc3 = fmaf(us, pv.w, acc3);
        }
        *(float4*)&redn[g][c4] = make_float4(acc0, acc1, acc2, acc3);
        __syncthreads();
        if (tid < SN) {
            float v = 0.f;
#pragma unroll
            for (int k = 0; k < 32; ++k) v += redn[k][tid];
            alpha_n[tid] = m + __logf(v) + em_n[t & 1][tid];
        }
        __syncthreads();
    }

    float a = (tid < SN) ? alpha_n[tid] + lf[b * SN + tid] : -1e30f;
    if (tid < 64) {
        float wm = warp_max(a);
        if (lane == 0) wred[tid >> 5] = wm;
    }
    __syncthreads();
    float m = fmaxf(wred[0], wred[1]);
    float e = (tid < SN) ? __expf(a - m) : 0.f;
    __syncthreads();
    if (tid < 64) {
        float ws = warp_sum(e);
        if (lane == 0) wred[tid >> 5] = ws;
    }
    __syncthreads();
    if (tid == 0) g_llh[BB + b] = m + __logf(wred[0] + wred[1]);
}

// Fused: clusters 0..15 (CTAs 0..127) = den; CTAs 128..143 = num batches 0..15.
__global__ void __launch_bounds__(512, 1) __cluster_dims__(CLU, 1, 1)
fused_kernel(const float* __restrict__ x, const int* __restrict__ seqlens,
             const float* __restrict__ num_logA, const float* __restrict__ num_ls,
             const float* __restrict__ num_lf, const int* __restrict__ num_ids,
             const float* __restrict__ den_logA, const float* __restrict__ den_ls,
             const float* __restrict__ den_lf, const int* __restrict__ den_ids) {
    if (blockIdx.x < BB * CLU)
        den_path(x, seqlens, den_logA, den_ls, den_lf, den_ids);
    else
        num_path(blockIdx.x - BB * CLU, x, seqlens, num_logA, num_ls, num_lf, num_ids);
}

__global__ void finalize_kernel(float* __restrict__ out) {
    float sden = 0.f, snum = 0.f;
    for (int i = 0; i < BB; ++i) {
        sden += g_llh[i];
        snum += g_llh[BB + i];
    }
    out[0] = -(snum - sden);
}

extern "C" void kernel_launch(void* const* d_in, const int* in_sizes, int n_in,
                              void* d_out, int out_size) {
    const float* x        = (const float*)d_in[0];
    const int*   seqlens  = (const int*)d_in[1];
    const float* num_logA = (const float*)d_in[2];
    const float* num_ls   = (const float*)d_in[3];
    const float* num_lf   = (const float*)d_in[4];
    const int*   num_ids  = (const int*)d_in[5];
    const float* den_logA = (const float*)d_in[6];
    const float* den_ls   = (const float*)d_in[7];
    const float* den_lf   = (const float*)d_in[8];
    const int*   den_ids  = (const int*)d_in[9];

    fused_kernel<<<BB * CLU + BB, 512>>>(x, seqlens, num_logA, num_ls, num_lf,
                                         num_ids, den_logA, den_ls, den_lf, den_ids);
    finalize_kernel<<<1, 1>>>((float*)d_out);
}